// round 16
// baseline (speedup 1.0000x reference)
#include <cuda_runtime.h>
#include <cuda_bf16.h>
#include <math.h>

#define B_ 4
#define S_ 2048
#define H_ 576
#define NH_ 9
#define NKV_ 3
#define HD_ 64
#define M_TOK (B_ * S_)   // 8192
#define K2_ (H_ / 2)      // 288 packed u32 per token row
#define NQKV (NH_ * HD_ + 2 * NKV_ * HD_)   // 960

// ---------------- scratch -----------------------------------------------------
__device__ float g_q[B_ * NH_ * S_ * HD_];
__device__ float g_k[B_ * NKV_ * S_ * HD_];
__device__ float g_v[B_ * NKV_ * S_ * HD_];
__device__ float g_cos[S_ * 32];
__device__ float g_sin[S_ * 32];

__device__ unsigned g_xh[M_TOK * K2_],  g_xl[M_TOK * K2_];
__device__ unsigned g_wqkvh[NQKV * K2_], g_wqkvl[NQKV * K2_];
__device__ unsigned g_woh[H_ * K2_],    g_wol[H_ * K2_];
__device__ unsigned g_qh[B_ * NH_ * S_ * 32],  g_ql[B_ * NH_ * S_ * 32];
__device__ unsigned g_kh[B_ * NKV_ * S_ * 32], g_kl[B_ * NKV_ * S_ * 32];
__device__ unsigned g_vth[B_ * NKV_ * HD_ * (S_ / 2)], g_vtl[B_ * NKV_ * HD_ * (S_ / 2)];
__device__ unsigned g_oh[M_TOK * K2_],  g_ol[M_TOK * K2_];

// ---------------- helpers ------------------------------------------------------
__device__ __forceinline__ void split_pack(float x0, float x1, unsigned& hi, unsigned& lo)
{
    __nv_bfloat162 h = __float22bfloat162_rn(make_float2(x0, x1));
    float2 hf = __bfloat1622float2(h);
    __nv_bfloat162 l = __float22bfloat162_rn(make_float2(x0 - hf.x, x1 - hf.y));
    hi = *reinterpret_cast<unsigned*>(&h);
    lo = *reinterpret_cast<unsigned*>(&l);
}

__device__ __forceinline__ void mma16(float* c,
    unsigned a0, unsigned a1, unsigned a2, unsigned a3,
    unsigned b0, unsigned b1)
{
    asm volatile(
        "mma.sync.aligned.m16n8k16.row.col.f32.bf16.bf16.f32 "
        "{%0,%1,%2,%3},{%4,%5,%6,%7},{%8,%9},{%0,%1,%2,%3};"
        : "+f"(c[0]), "+f"(c[1]), "+f"(c[2]), "+f"(c[3])
        : "r"(a0), "r"(a1), "r"(a2), "r"(a3), "r"(b0), "r"(b1));
}
__device__ __forceinline__ void mma_split(float* c,
    const unsigned* ah, const unsigned* al,
    const unsigned* bh, const unsigned* bl)
{
    mma16(c, ah[0], ah[1], ah[2], ah[3], bh[0], bh[1]);
    mma16(c, ah[0], ah[1], ah[2], ah[3], bl[0], bl[1]);
    mma16(c, al[0], al[1], al[2], al[3], bh[0], bh[1]);
}

__device__ __forceinline__ void ldsm4(unsigned* r, const unsigned* p)
{
    unsigned addr = (unsigned)__cvta_generic_to_shared(p);
    asm volatile("ldmatrix.sync.aligned.m8n8.x4.shared.b16 {%0,%1,%2,%3}, [%4];"
        : "=r"(r[0]), "=r"(r[1]), "=r"(r[2]), "=r"(r[3]) : "r"(addr));
}

__device__ __forceinline__ void cp16(unsigned* dst, const unsigned* src)
{
    unsigned addr = (unsigned)__cvta_generic_to_shared(dst);
    asm volatile("cp.async.cg.shared.global [%0], [%1], 16;" :: "r"(addr), "l"(src));
}
#define CP_COMMIT() asm volatile("cp.async.commit_group;")
#define CP_WAIT1()  asm volatile("cp.async.wait_group 1;")
#define CP_WAIT0()  asm volatile("cp.async.wait_group 0;")

// ---------------- fused prepass: split-pack x + stacked Wqkv + Wo ---------------
#define N0 (M_TOK * K2_)
#define N1 (H_ * K2_)
#define N2 (NKV_ * HD_ * K2_)
__global__ void split_pack_all(
    const float* __restrict__ x,  const float* __restrict__ wq,
    const float* __restrict__ wk, const float* __restrict__ wv,
    const float* __restrict__ wo)
{
    int i = blockIdx.x * blockDim.x + threadIdx.x;
    const float* src; unsigned *hi, *lo; int j;
    if (i < N0)                        { src = x;  hi = g_xh;    lo = g_xl;    j = i; }
    else if (i < N0 + N1)              { src = wq; hi = g_wqkvh; lo = g_wqkvl; j = i - N0; }
    else if (i < N0 + N1 + N2)         { src = wk; hi = g_wqkvh + N1;      lo = g_wqkvl + N1;      j = i - N0 - N1; }
    else if (i < N0 + N1 + 2 * N2)     { src = wv; hi = g_wqkvh + N1 + N2; lo = g_wqkvl + N1 + N2; j = i - N0 - N1 - N2; }
    else if (i < N0 + 2 * N1 + 2 * N2) { src = wo; hi = g_woh;   lo = g_wol;   j = i - N0 - N1 - 2 * N2; }
    else return;
    float2 v = ((const float2*)src)[j];
    split_pack(v.x, v.y, hi[j], lo[j]);
}

// ---------------- tensor-core GEMM, cp.async double-buffered, 2 CTAs/SM ---------
#define GST 36
#define GBUF 13824
#define GEMM_SMEM (2 * GBUF * 4)

__global__ __launch_bounds__(256, 2) void gemm_tc(
    const unsigned* __restrict__ Ahg, const unsigned* __restrict__ Alg,
    const unsigned* __restrict__ Whg, const unsigned* __restrict__ Wlg,
    float* __restrict__ C, int N, int K2, int mode)
{
    extern __shared__ unsigned smu[];

    const int tid = threadIdx.x;
    const int w = tid >> 5;
    const int lane = tid & 31;
    const int g = lane >> 2;
    const int t = lane & 3;
    const int wm = w >> 1;
    const int wn = w & 1;
    const int m0 = blockIdx.y * 128;
    const int n0 = blockIdx.x * 64;

    const int a_row = lane & 15;
    const int a_col = (lane >> 4) << 2;
    const int b_row = (((lane >> 4) & 1) << 3) + (lane & 7);
    const int b_col = ((lane >> 3) & 1) << 2;

    const int nks = K2 / 32;

    auto issue = [&](int ks, int buf) {
        unsigned* Ah = smu + buf * GBUF;
        unsigned* Al = Ah + 128 * GST;
        unsigned* Wh = Al + 128 * GST;
        unsigned* Wl = Wh + 64 * GST;
        int k2 = ks * 32;
#pragma unroll
        for (int i = tid; i < 128 * 8; i += 256) {
            int r = i >> 3, c4 = (i & 7) << 2;
            cp16(&Ah[r * GST + c4], &Ahg[(size_t)(m0 + r) * K2 + k2 + c4]);
            cp16(&Al[r * GST + c4], &Alg[(size_t)(m0 + r) * K2 + k2 + c4]);
        }
#pragma unroll
        for (int i = tid; i < 64 * 8; i += 256) {
            int r = i >> 3, c4 = (i & 7) << 2;
            cp16(&Wh[r * GST + c4], &Whg[(size_t)(n0 + r) * K2 + k2 + c4]);
            cp16(&Wl[r * GST + c4], &Wlg[(size_t)(n0 + r) * K2 + k2 + c4]);
        }
    };

    float acc[2][4][4];
#pragma unroll
    for (int mt = 0; mt < 2; mt++)
#pragma unroll
        for (int nt = 0; nt < 4; nt++)
#pragma unroll
            for (int r = 0; r < 4; r++) acc[mt][nt][r] = 0.f;

    issue(0, 0);
    CP_COMMIT();

    for (int ks = 0; ks < nks; ks++) {
        if (ks + 1 < nks) { issue(ks + 1, (ks + 1) & 1); CP_COMMIT(); CP_WAIT1(); }
        else              { CP_WAIT0(); }
        __syncthreads();

        unsigned* Ah = smu + (ks & 1) * GBUF;
        unsigned* Al = Ah + 128 * GST;
        unsigned* Wh = Al + 128 * GST;
        unsigned* Wl = Wh + 64 * GST;

#pragma unroll
        for (int kk = 0; kk < 4; kk++) {
            const int k8 = kk * 8;
            unsigned ah[2][4], al[2][4], bh[2][4], bl[2][4];
#pragma unroll
            for (int mt = 0; mt < 2; mt++) {
                int R = wm * 32 + mt * 16;
                ldsm4(ah[mt], &Ah[(R + a_row) * GST + k8 + a_col]);
                ldsm4(al[mt], &Al[(R + a_row) * GST + k8 + a_col]);
            }
#pragma unroll
            for (int np = 0; np < 2; np++) {
                int Cc = wn * 32 + np * 16;
                ldsm4(bh[np], &Wh[(Cc + b_row) * GST + k8 + b_col]);
                ldsm4(bl[np], &Wl[(Cc + b_row) * GST + k8 + b_col]);
            }
#pragma unroll
            for (int mt = 0; mt < 2; mt++)
#pragma unroll
                for (int np = 0; np < 2; np++) {
                    mma_split(acc[mt][2 * np],     ah[mt], al[mt], bh[np],     bl[np]);
                    mma_split(acc[mt][2 * np + 1], ah[mt], al[mt], bh[np] + 2, bl[np] + 2);
                }
        }
        __syncthreads();
    }

#pragma unroll
    for (int mt = 0; mt < 2; mt++)
#pragma unroll
        for (int nt = 0; nt < 4; nt++)
#pragma unroll
            for (int r = 0; r < 4; r++) {
                int row = m0 + wm * 32 + mt * 16 + g + ((r >> 1) << 3);
                int col = n0 + wn * 32 + nt * 8 + t * 2 + (r & 1);
                float v = acc[mt][nt][r];
                if (mode == 0) {
                    int b = row / S_, s = row - b * S_;
                    if (col < NH_ * HD_) {
                        int h = col >> 6, d = col & 63;
                        g_q[(((size_t)b * NH_ + h) * S_ + s) * HD_ + d] = v;
                    } else if (col < NH_ * HD_ + NKV_ * HD_) {
                        int c = col - NH_ * HD_;
                        int h = c >> 6, d = c & 63;
                        g_k[(((size_t)b * NKV_ + h) * S_ + s) * HD_ + d] = v;
                    } else {
                        int c = col - NH_ * HD_ - NKV_ * HD_;
                        int h = c >> 6, d = c & 63;
                        g_v[(((size_t)b * NKV_ + h) * S_ + s) * HD_ + d] = v;
                    }
                } else {
                    C[(size_t)row * N + col] = v;
                }
            }
}

// ---------------- RoPE ----------------------------------------------------------
__global__ void rope_table_kernel()
{
    int idx = blockIdx.x * blockDim.x + threadIdx.x;
    if (idx >= S_ * 32) return;
    int j = idx & 31;
    int s = idx >> 5;
    double invf = pow(100000.0, -(double)(2 * j) / 64.0);
    double ang = (double)s * invf;
    g_cos[idx] = (float)cos(ang);
    g_sin[idx] = (float)sin(ang);
}

// fused q+k rope+pack, 8 threads/row, float4 loads.
__global__ void rope_apply_pack_all(int rows_q, int rows_k)
{
    int idx = blockIdx.x * blockDim.x + threadIdx.x;
    int j = idx & 7;
    int row = idx >> 3;
    const float* buf; unsigned *oh, *ol; float scale;
    if (row < rows_q) { buf = g_q; oh = g_qh; ol = g_ql; scale = 0.125f * 1.44269504088896f; }
    else if (row < rows_q + rows_k) { row -= rows_q; buf = g_k; oh = g_kh; ol = g_kl; scale = 1.0f; }
    else return;
    int s = row & (S_ - 1);
    const float* p = buf + (size_t)row * HD_;
    int jj = 4 * j;
    float4 c  = *(const float4*)&g_cos[s * 32 + jj];
    float4 sn = *(const float4*)&g_sin[s * 32 + jj];
    float4 xa = *(const float4*)&p[jj];
    float4 xb = *(const float4*)&p[jj + 32];

    float y0 = (xa.x * c.x - xb.x * sn.x) * scale;
    float y1 = (xa.y * c.y - xb.y * sn.y) * scale;
    float y2 = (xa.z * c.z - xb.z * sn.z) * scale;
    float y3 = (xa.w * c.w - xb.w * sn.w) * scale;
    float z0 = (xb.x * c.x + xa.x * sn.x) * scale;
    float z1 = (xb.y * c.y + xa.y * sn.y) * scale;
    float z2 = (xb.z * c.z + xa.z * sn.z) * scale;
    float z3 = (xb.w * c.w + xa.w * sn.w) * scale;

    unsigned h0, l0u, h1, l1u;
    split_pack(y0, y1, h0, l0u);
    split_pack(y2, y3, h1, l1u);
    *(uint2*)&oh[(size_t)row * 32 + 2 * j] = make_uint2(h0, h1);
    *(uint2*)&ol[(size_t)row * 32 + 2 * j] = make_uint2(l0u, l1u);
    split_pack(z0, z1, h0, l0u);
    split_pack(z2, z3, h1, l1u);
    *(uint2*)&oh[(size_t)row * 32 + 16 + 2 * j] = make_uint2(h0, h1);
    *(uint2*)&ol[(size_t)row * 32 + 16 + 2 * j] = make_uint2(l0u, l1u);
}

// ---------------- V transpose + pack ----------------------------------------------
#define VTS 68
__global__ __launch_bounds__(256) void vpack_kernel(
    const float* __restrict__ V, unsigned* __restrict__ vh, unsigned* __restrict__ vl)
{
    __shared__ float sm[64 * VTS];
    const int bh = blockIdx.y;
    const int k0 = blockIdx.x * 64;
    const int tid = threadIdx.x;
    const float* src = V + ((size_t)bh * S_ + k0) * HD_;
    for (int i = tid; i < 64 * 16; i += 256) {
        int r = i >> 4, d4 = (i & 15) << 2;
        *(float4*)&sm[r * VTS + d4] = *(const float4*)&src[r * HD_ + d4];
    }
    __syncthreads();
    for (int i = tid; i < 64 * 32; i += 256) {
        int d = i >> 5, c = i & 31;
        float v0 = sm[(2 * c) * VTS + d];
        float v1 = sm[(2 * c + 1) * VTS + d];
        unsigned hi, lo;
        split_pack(v0, v1, hi, lo);
        size_t o = ((size_t)bh * HD_ + d) * (S_ / 2) + k0 / 2 + c;
        vh[o] = hi; vl[o] = lo;
    }
}

// ---------------- Flash attention (fixed-max exp2, interleaved PV, warp-skip) -----
#define MFIX 16.0f
#define AST 36
#define OFF_Q 0
#define KVBUF 9216
#define OFF_KV 9216
#define ATT_SMEM ((OFF_KV + 2 * KVBUF) * 4)

__global__ __launch_bounds__(256, 2) void attn_tc_kernel(
    const unsigned* __restrict__ Qh, const unsigned* __restrict__ Ql,
    const unsigned* __restrict__ Kh, const unsigned* __restrict__ Kl,
    const unsigned* __restrict__ Vth, const unsigned* __restrict__ Vtl,
    unsigned* __restrict__ Ohg, unsigned* __restrict__ Olg)
{
    extern __shared__ unsigned smu[];
    unsigned* sQh = smu + OFF_Q;
    unsigned* sQl = sQh + 128 * AST;

    const int bh = blockIdx.y;
    const int b = bh / NH_;
    const int h = bh - b * NH_;
    const int kvh = h / (NH_ / NKV_);
    const int q0 = (gridDim.x - 1 - blockIdx.x) * 128;

    const int tid = threadIdx.x;
    const int w = tid >> 5;
    const int lane = tid & 31;
    const int g = lane >> 2;
    const int t = lane & 3;
    const int R0 = w * 16;

    const int a_row = lane & 15;
    const int a_col = (lane >> 4) << 2;
    const int b_row = (((lane >> 4) & 1) << 3) + (lane & 7);
    const int b_col = ((lane >> 3) & 1) << 2;

    const unsigned* Qbh = Qh + ((size_t)bh * S_ + q0) * 32;
    const unsigned* Qbl = Ql + ((size_t)bh * S_ + q0) * 32;
    const unsigned* Kbh = Kh + ((size_t)(b * NKV_ + kvh) * S_) * 32;
    const unsigned* Kbl = Kl + ((size_t)(b * NKV_ + kvh) * S_) * 32;
    const unsigned* Vbh = Vth + (size_t)(b * NKV_ + kvh) * HD_ * (S_ / 2);
    const unsigned* Vbl = Vtl + (size_t)(b * NKV_ + kvh) * HD_ * (S_ / 2);

    const int nkt = q0 / 64 + 2;

    auto issue_kv = [&](int kt, int buf) {
        unsigned* base = smu + OFF_KV + buf * KVBUF;
        unsigned* dKh = base;
        unsigned* dKl = base + 2304;
        unsigned* dVh = base + 4608;
        unsigned* dVl = base + 6912;
        const int k0 = kt * 64;
#pragma unroll
        for (int i = tid; i < 2048; i += 256) {
            int sel = i >> 9;
            int j = i & 511;
            int r = j >> 3, c4 = (j & 7) << 2;
            if (sel == 0)      cp16(&dKh[r * AST + c4], &Kbh[(size_t)(k0 + r) * 32 + c4]);
            else if (sel == 1) cp16(&dKl[r * AST + c4], &Kbl[(size_t)(k0 + r) * 32 + c4]);
            else if (sel == 2) cp16(&dVh[r * AST + c4], &Vbh[(size_t)r * (S_ / 2) + k0 / 2 + c4]);
            else               cp16(&dVl[r * AST + c4], &Vbl[(size_t)r * (S_ / 2) + k0 / 2 + c4]);
        }
    };

#pragma unroll
    for (int i = tid; i < 128 * 8; i += 256) {
        int r = i >> 3, c4 = (i & 7) << 2;
        cp16(&sQh[r * AST + c4], &Qbh[(size_t)r * 32 + c4]);
        cp16(&sQl[r * AST + c4], &Qbl[(size_t)r * 32 + c4]);
    }
    issue_kv(0, 0);
    CP_COMMIT();

    float acc[8][4];
#pragma unroll
    for (int nt = 0; nt < 8; nt++)
#pragma unroll
        for (int r = 0; r < 4; r++) acc[nt][r] = 0.f;

    float l0 = 0.f, l1 = 0.f;

    for (int kt = 0; kt < nkt; kt++) {
        const int k0 = kt * 64;
        if (kt + 1 < nkt) { issue_kv(kt + 1, (kt + 1) & 1); CP_COMMIT(); CP_WAIT1(); }
        else              { CP_WAIT0(); }
        __syncthreads();

        const bool active = !(kt == nkt - 1 && R0 < 49);

        if (active) {
            unsigned* base = smu + OFF_KV + (kt & 1) * KVBUF;
            unsigned* sKh = base;
            unsigned* sKl = base + 2304;
            unsigned* sVh = base + 4608;
            unsigned* sVl = base + 6912;

            float sacc[8][4];
#pragma unroll
            for (int nt = 0; nt < 8; nt++)
#pragma unroll
                for (int r = 0; r < 4; r++) sacc[nt][r] = 0.f;

#pragma unroll
            for (int kk = 0; kk < 4; kk++) {
                const int k8 = kk * 8;
                unsigned qh[4], ql[4];
                ldsm4(qh, &sQh[(R0 + a_row) * AST + k8 + a_col]);
                ldsm4(ql, &sQl[(R0 + a_row) * AST + k8 + a_col]);
#pragma unroll
                for (int np = 0; np < 4; np++) {
                    unsigned kh4[4], kl4[4];
                    ldsm4(kh4, &sKh[(np * 16 + b_row) * AST + k8 + b_col]);
                    ldsm4(kl4, &sKl[(np * 16 + b_row) * AST + k8 + b_col]);
                    mma_split(sacc[2 * np],     qh, ql, kh4,     kl4);
                    mma_split(sacc[2 * np + 1], qh, ql, kh4 + 2, kl4 + 2);
                }
            }

            if (kt >= nkt - 2) {
                int row0 = q0 + R0 + g;
                int row1 = row0 + 8;
#pragma unroll
                for (int nt = 0; nt < 8; nt++) {
                    int col = k0 + nt * 8 + 2 * t;
                    if (col > row0)     sacc[nt][0] = -1e30f;
                    if (col + 1 > row0) sacc[nt][1] = -1e30f;
                    if (col > row1)     sacc[nt][2] = -1e30f;
                    if (col + 1 > row1) sacc[nt][3] = -1e30f;
                }
            }

#pragma unroll
            for (int kk = 0; kk < 4; kk++) {
                float* s0 = sacc[2 * kk];
                float* s1 = sacc[2 * kk + 1];
                s0[0] = exp2f(s0[0] - MFIX);
                s0[1] = exp2f(s0[1] - MFIX);
                s0[2] = exp2f(s0[2] - MFIX);
                s0[3] = exp2f(s0[3] - MFIX);
                s1[0] = exp2f(s1[0] - MFIX);
                s1[1] = exp2f(s1[1] - MFIX);
                s1[2] = exp2f(s1[2] - MFIX);
                s1[3] = exp2f(s1[3] - MFIX);
                l0 += s0[0] + s0[1] + s1[0] + s1[1];
                l1 += s0[2] + s0[3] + s1[2] + s1[3];

                unsigned ph[4], pl[4];
                split_pack(s0[0], s0[1], ph[0], pl[0]);
                split_pack(s0[2], s0[3], ph[1], pl[1]);
                split_pack(s1[0], s1[1], ph[2], pl[2]);
                split_pack(s1[2], s1[3], ph[3], pl[3]);
                const int k8 = kk * 8;
#pragma unroll
                for (int np = 0; np < 4; np++) {
                    unsigned vh4[4], vl4[4];
                    ldsm4(vh4, &sVh[(np * 16 + b_row) * AST + k8 + b_col]);
                    ldsm4(vl4, &sVl[(np * 16 + b_row) * AST + k8 + b_col]);
                    mma_split(acc[2 * np],     ph, pl, vh4,     vl4);
                    mma_split(acc[2 * np + 1], ph, pl, vh4 + 2, vl4 + 2);
                }
            }
        }
        __syncthreads();
    }

    l0 += __shfl_xor_sync(0xffffffffu, l0, 1);
    l0 += __shfl_xor_sync(0xffffffffu, l0, 2);
    l1 += __shfl_xor_sync(0xffffffffu, l1, 1);
    l1 += __shfl_xor_sync(0xffffffffu, l1, 2);

    float inv0 = 1.f / l0;
    float inv1 = 1.f / l1;
    int row0 = q0 + R0 + g;
    int row1 = row0 + 8;
    size_t tok0 = (size_t)b * S_ + row0;
    size_t tok1 = (size_t)b * S_ + row1;
#pragma unroll
    for (int nt = 0; nt < 8; nt++) {
        int col2 = h * 32 + nt * 4 + t;
        unsigned hi, lo;
        split_pack(acc[nt][0] * inv0, acc[nt][1] * inv0, hi, lo);
        Ohg[tok0 * K2_ + col2] = hi;
        Olg[tok0 * K2_ + col2] = lo;
        split_pack(acc[nt][2] * inv1, acc[nt][3] * inv1, hi, lo);
        Ohg[tok1 * K2_ + col2] = hi;
        Olg[tok1 * K2_ + col2] = lo;
    }
}

// ---------------- launch ----------------------------------------------------------
extern "C" void kernel_launch(void* const* d_in, const int* in_sizes, int n_in,
                              void* d_out, int out_size)
{
    const float* x  = (const float*)d_in[0];
    const float* Wq = (const float*)d_in[1];
    const float* Wk = (const float*)d_in[2];
    const float* Wv = (const float*)d_in[3];
    const float* Wo = (const float*)d_in[4];
    float* out = (float*)d_out;

    float *vp;
    unsigned *xh, *xl, *wqkvh, *wqkvl, *woh, *wol;
    unsigned *qh, *ql, *kh, *kl, *vth, *vtl, *oh, *ol;
    cudaGetSymbolAddress((void**)&vp, g_v);
    cudaGetSymbolAddress((void**)&xh, g_xh);       cudaGetSymbolAddress((void**)&xl, g_xl);
    cudaGetSymbolAddress((void**)&wqkvh, g_wqkvh); cudaGetSymbolAddress((void**)&wqkvl, g_wqkvl);
    cudaGetSymbolAddress((void**)&woh, g_woh);     cudaGetSymbolAddress((void**)&wol, g_wol);
    cudaGetSymbolAddress((void**)&qh, g_qh);       cudaGetSymbolAddress((void**)&ql, g_ql);
    cudaGetSymbolAddress((void**)&kh, g_kh);       cudaGetSymbolAddress((void**)&kl, g_kl);
    cudaGetSymbolAddress((void**)&vth, g_vth);     cudaGetSymbolAddress((void**)&vtl, g_vtl);
    cudaGetSymbolAddress((void**)&oh, g_oh);       cudaGetSymbolAddress((void**)&ol, g_ol);

    rope_table_kernel<<<(S_ * 32 + 255) / 256, 256>>>();

    {
        int total = N0 + 2 * N1 + 2 * N2;
        split_pack_all<<<(total + 255) / 256, 256>>>(x, Wq, Wk, Wv, Wo);
    }

    cudaFuncSetAttribute(gemm_tc, cudaFuncAttributeMaxDynamicSharedMemorySize, GEMM_SMEM);

    gemm_tc<<<dim3(NQKV / 64, M_TOK / 128), 256, GEMM_SMEM>>>(xh, xl, wqkvh, wqkvl, nullptr, NQKV, K2_, 0);

    {
        int rows_q = B_ * NH_ * S_;
        int rows_k = B_ * NKV_ * S_;
        rope_apply_pack_all<<<((rows_q + rows_k) * 8 + 255) / 256, 256>>>(rows_q, rows_k);
    }

    vpack_kernel<<<dim3(S_ / 64, B_ * NKV_), 256>>>(vp, vth, vtl);

    cudaFuncSetAttribute(attn_tc_kernel, cudaFuncAttributeMaxDynamicSharedMemorySize, ATT_SMEM);
    attn_tc_kernel<<<dim3(S_ / 128, B_ * NH_), 256, ATT_SMEM>>>(qh, ql, kh, kl, vth, vtl, oh, ol);

    gemm_tc<<<dim3(H_ / 64, M_TOK / 128), 256, GEMM_SMEM>>>(oh, ol, woh, wol, out, H_, K2_, 1);
}

// round 17
// speedup vs baseline: 1.0163x; 1.0163x over previous
#include <cuda_runtime.h>
#include <cuda_bf16.h>
#include <math.h>

#define B_ 4
#define S_ 2048
#define H_ 576
#define NH_ 9
#define NKV_ 3
#define HD_ 64
#define M_TOK (B_ * S_)   // 8192
#define K2_ (H_ / 2)      // 288 packed u32 per token row
#define NQKV (NH_ * HD_ + 2 * NKV_ * HD_)   // 960

// ---------------- scratch -----------------------------------------------------
__device__ float g_q[B_ * NH_ * S_ * HD_];
__device__ float g_k[B_ * NKV_ * S_ * HD_];
__device__ float g_v[B_ * NKV_ * S_ * HD_];
__device__ float g_cos[S_ * 32];
__device__ float g_sin[S_ * 32];

__device__ unsigned g_xh[M_TOK * K2_],  g_xl[M_TOK * K2_];
__device__ unsigned g_wqkvh[NQKV * K2_], g_wqkvl[NQKV * K2_];
__device__ unsigned g_woh[H_ * K2_],    g_wol[H_ * K2_];
__device__ unsigned g_qh[B_ * NH_ * S_ * 32],  g_ql[B_ * NH_ * S_ * 32];
__device__ unsigned g_kh[B_ * NKV_ * S_ * 32], g_kl[B_ * NKV_ * S_ * 32];
__device__ unsigned g_vth[B_ * NKV_ * HD_ * (S_ / 2)], g_vtl[B_ * NKV_ * HD_ * (S_ / 2)];
__device__ unsigned g_oh[M_TOK * K2_],  g_ol[M_TOK * K2_];

// ---------------- helpers ------------------------------------------------------
__device__ __forceinline__ void split_pack(float x0, float x1, unsigned& hi, unsigned& lo)
{
    __nv_bfloat162 h = __float22bfloat162_rn(make_float2(x0, x1));
    float2 hf = __bfloat1622float2(h);
    __nv_bfloat162 l = __float22bfloat162_rn(make_float2(x0 - hf.x, x1 - hf.y));
    hi = *reinterpret_cast<unsigned*>(&h);
    lo = *reinterpret_cast<unsigned*>(&l);
}

__device__ __forceinline__ void mma16(float* c,
    unsigned a0, unsigned a1, unsigned a2, unsigned a3,
    unsigned b0, unsigned b1)
{
    asm volatile(
        "mma.sync.aligned.m16n8k16.row.col.f32.bf16.bf16.f32 "
        "{%0,%1,%2,%3},{%4,%5,%6,%7},{%8,%9},{%0,%1,%2,%3};"
        : "+f"(c[0]), "+f"(c[1]), "+f"(c[2]), "+f"(c[3])
        : "r"(a0), "r"(a1), "r"(a2), "r"(a3), "r"(b0), "r"(b1));
}
__device__ __forceinline__ void mma_split(float* c,
    const unsigned* ah, const unsigned* al,
    const unsigned* bh, const unsigned* bl)
{
    mma16(c, ah[0], ah[1], ah[2], ah[3], bh[0], bh[1]);
    mma16(c, ah[0], ah[1], ah[2], ah[3], bl[0], bl[1]);
    mma16(c, al[0], al[1], al[2], al[3], bh[0], bh[1]);
}

__device__ __forceinline__ void ldsm4(unsigned* r, const unsigned* p)
{
    unsigned addr = (unsigned)__cvta_generic_to_shared(p);
    asm volatile("ldmatrix.sync.aligned.m8n8.x4.shared.b16 {%0,%1,%2,%3}, [%4];"
        : "=r"(r[0]), "=r"(r[1]), "=r"(r[2]), "=r"(r[3]) : "r"(addr));
}

__device__ __forceinline__ void cp16(unsigned* dst, const unsigned* src)
{
    unsigned addr = (unsigned)__cvta_generic_to_shared(dst);
    asm volatile("cp.async.cg.shared.global [%0], [%1], 16;" :: "r"(addr), "l"(src));
}
#define CP_COMMIT() asm volatile("cp.async.commit_group;")
#define CP_WAIT1()  asm volatile("cp.async.wait_group 1;")
#define CP_WAIT0()  asm volatile("cp.async.wait_group 0;")

// ---------------- fused prepass: split-pack x + stacked Wqkv + Wo ---------------
#define N0 (M_TOK * K2_)
#define N1 (H_ * K2_)
#define N2 (NKV_ * HD_ * K2_)
__global__ void split_pack_all(
    const float* __restrict__ x,  const float* __restrict__ wq,
    const float* __restrict__ wk, const float* __restrict__ wv,
    const float* __restrict__ wo)
{
    int i = blockIdx.x * blockDim.x + threadIdx.x;
    const float* src; unsigned *hi, *lo; int j;
    if (i < N0)                        { src = x;  hi = g_xh;    lo = g_xl;    j = i; }
    else if (i < N0 + N1)              { src = wq; hi = g_wqkvh; lo = g_wqkvl; j = i - N0; }
    else if (i < N0 + N1 + N2)         { src = wk; hi = g_wqkvh + N1;      lo = g_wqkvl + N1;      j = i - N0 - N1; }
    else if (i < N0 + N1 + 2 * N2)     { src = wv; hi = g_wqkvh + N1 + N2; lo = g_wqkvl + N1 + N2; j = i - N0 - N1 - N2; }
    else if (i < N0 + 2 * N1 + 2 * N2) { src = wo; hi = g_woh;   lo = g_wol;   j = i - N0 - N1 - 2 * N2; }
    else return;
    float2 v = ((const float2*)src)[j];
    split_pack(v.x, v.y, hi[j], lo[j]);
}

// ---------------- tensor-core GEMM, cp.async double-buffered --------------------
#define GST 36
#define GBUF 13824
#define GEMM_SMEM (2 * GBUF * 4)

__global__ __launch_bounds__(256) void gemm_tc(
    const unsigned* __restrict__ Ahg, const unsigned* __restrict__ Alg,
    const unsigned* __restrict__ Whg, const unsigned* __restrict__ Wlg,
    float* __restrict__ C, int N, int K2, int mode)
{
    extern __shared__ unsigned smu[];

    const int tid = threadIdx.x;
    const int w = tid >> 5;
    const int lane = tid & 31;
    const int g = lane >> 2;
    const int t = lane & 3;
    const int wm = w >> 1;
    const int wn = w & 1;
    const int m0 = blockIdx.y * 128;
    const int n0 = blockIdx.x * 64;

    const int a_row = lane & 15;
    const int a_col = (lane >> 4) << 2;
    const int b_row = (((lane >> 4) & 1) << 3) + (lane & 7);
    const int b_col = ((lane >> 3) & 1) << 2;

    const int nks = K2 / 32;

    auto issue = [&](int ks, int buf) {
        unsigned* Ah = smu + buf * GBUF;
        unsigned* Al = Ah + 128 * GST;
        unsigned* Wh = Al + 128 * GST;
        unsigned* Wl = Wh + 64 * GST;
        int k2 = ks * 32;
#pragma unroll
        for (int i = tid; i < 128 * 8; i += 256) {
            int r = i >> 3, c4 = (i & 7) << 2;
            cp16(&Ah[r * GST + c4], &Ahg[(size_t)(m0 + r) * K2 + k2 + c4]);
            cp16(&Al[r * GST + c4], &Alg[(size_t)(m0 + r) * K2 + k2 + c4]);
        }
#pragma unroll
        for (int i = tid; i < 64 * 8; i += 256) {
            int r = i >> 3, c4 = (i & 7) << 2;
            cp16(&Wh[r * GST + c4], &Whg[(size_t)(n0 + r) * K2 + k2 + c4]);
            cp16(&Wl[r * GST + c4], &Wlg[(size_t)(n0 + r) * K2 + k2 + c4]);
        }
    };

    float acc[2][4][4];
#pragma unroll
    for (int mt = 0; mt < 2; mt++)
#pragma unroll
        for (int nt = 0; nt < 4; nt++)
#pragma unroll
            for (int r = 0; r < 4; r++) acc[mt][nt][r] = 0.f;

    issue(0, 0);
    CP_COMMIT();

    for (int ks = 0; ks < nks; ks++) {
        if (ks + 1 < nks) { issue(ks + 1, (ks + 1) & 1); CP_COMMIT(); CP_WAIT1(); }
        else              { CP_WAIT0(); }
        __syncthreads();

        unsigned* Ah = smu + (ks & 1) * GBUF;
        unsigned* Al = Ah + 128 * GST;
        unsigned* Wh = Al + 128 * GST;
        unsigned* Wl = Wh + 64 * GST;

#pragma unroll
        for (int kk = 0; kk < 4; kk++) {
            const int k8 = kk * 8;
            unsigned ah[2][4], al[2][4], bh[2][4], bl[2][4];
#pragma unroll
            for (int mt = 0; mt < 2; mt++) {
                int R = wm * 32 + mt * 16;
                ldsm4(ah[mt], &Ah[(R + a_row) * GST + k8 + a_col]);
                ldsm4(al[mt], &Al[(R + a_row) * GST + k8 + a_col]);
            }
#pragma unroll
            for (int np = 0; np < 2; np++) {
                int Cc = wn * 32 + np * 16;
                ldsm4(bh[np], &Wh[(Cc + b_row) * GST + k8 + b_col]);
                ldsm4(bl[np], &Wl[(Cc + b_row) * GST + k8 + b_col]);
            }
#pragma unroll
            for (int mt = 0; mt < 2; mt++)
#pragma unroll
                for (int np = 0; np < 2; np++) {
                    mma_split(acc[mt][2 * np],     ah[mt], al[mt], bh[np],     bl[np]);
                    mma_split(acc[mt][2 * np + 1], ah[mt], al[mt], bh[np] + 2, bl[np] + 2);
                }
        }
        __syncthreads();
    }

#pragma unroll
    for (int mt = 0; mt < 2; mt++)
#pragma unroll
        for (int nt = 0; nt < 4; nt++)
#pragma unroll
            for (int r = 0; r < 4; r++) {
                int row = m0 + wm * 32 + mt * 16 + g + ((r >> 1) << 3);
                int col = n0 + wn * 32 + nt * 8 + t * 2 + (r & 1);
                float v = acc[mt][nt][r];
                if (mode == 0) {
                    int b = row / S_, s = row - b * S_;
                    if (col < NH_ * HD_) {
                        int h = col >> 6, d = col & 63;
                        g_q[(((size_t)b * NH_ + h) * S_ + s) * HD_ + d] = v;
                    } else if (col < NH_ * HD_ + NKV_ * HD_) {
                        int c = col - NH_ * HD_;
                        int h = c >> 6, d = c & 63;
                        g_k[(((size_t)b * NKV_ + h) * S_ + s) * HD_ + d] = v;
                    } else {
                        int c = col - NH_ * HD_ - NKV_ * HD_;
                        int h = c >> 6, d = c & 63;
                        g_v[(((size_t)b * NKV_ + h) * S_ + s) * HD_ + d] = v;
                    }
                } else {
                    C[(size_t)row * N + col] = v;
                }
            }
}

// ---------------- RoPE table ------------------------------------------------------
__global__ void rope_table_kernel()
{
    int idx = blockIdx.x * blockDim.x + threadIdx.x;
    if (idx >= S_ * 32) return;
    int j = idx & 31;
    int s = idx >> 5;
    double invf = pow(100000.0, -(double)(2 * j) / 64.0);
    double ang = (double)s * invf;
    g_cos[idx] = (float)cos(ang);
    g_sin[idx] = (float)sin(ang);
}

// ---------------- fused rope(q,k) + vpack -------------------------------------------
// grid.x blocks: [0, RB_Q) rope-q, [RB_Q, RB_QK) rope-k, [RB_QK, RB_QK+VB) vpack
#define ROWS_Q (B_ * NH_ * S_)
#define ROWS_K (B_ * NKV_ * S_)
#define RB_Q  ((ROWS_Q * 8) / 256)          // 2304
#define RB_K  ((ROWS_K * 8) / 256)          // 768
#define RB_QK (RB_Q + RB_K)
#define VB    ((S_ / 64) * (B_ * NKV_))     // 384
#define VTS 68

__global__ __launch_bounds__(256) void rope_vpack_kernel()
{
    __shared__ float sm[64 * VTS];
    const int blk = blockIdx.x;
    const int tid = threadIdx.x;

    if (blk < RB_QK) {
        // ---- rope + pack path (8 threads per row, float4)
        int idx = blk * 256 + tid;
        int j = idx & 7;
        int row = idx >> 3;
        const float* buf; unsigned *oh, *ol; float scale;
        if (row < ROWS_Q) { buf = g_q; oh = g_qh; ol = g_ql; scale = 0.125f * 1.44269504088896f; }
        else              { row -= ROWS_Q; buf = g_k; oh = g_kh; ol = g_kl; scale = 1.0f; }
        int s = row & (S_ - 1);
        const float* p = buf + (size_t)row * HD_;
        int jj = 4 * j;
        float4 c  = *(const float4*)&g_cos[s * 32 + jj];
        float4 sn = *(const float4*)&g_sin[s * 32 + jj];
        float4 xa = *(const float4*)&p[jj];
        float4 xb = *(const float4*)&p[jj + 32];

        float y0 = (xa.x * c.x - xb.x * sn.x) * scale;
        float y1 = (xa.y * c.y - xb.y * sn.y) * scale;
        float y2 = (xa.z * c.z - xb.z * sn.z) * scale;
        float y3 = (xa.w * c.w - xb.w * sn.w) * scale;
        float z0 = (xb.x * c.x + xa.x * sn.x) * scale;
        float z1 = (xb.y * c.y + xa.y * sn.y) * scale;
        float z2 = (xb.z * c.z + xa.z * sn.z) * scale;
        float z3 = (xb.w * c.w + xa.w * sn.w) * scale;

        unsigned h0, l0u, h1, l1u;
        split_pack(y0, y1, h0, l0u);
        split_pack(y2, y3, h1, l1u);
        *(uint2*)&oh[(size_t)row * 32 + 2 * j] = make_uint2(h0, h1);
        *(uint2*)&ol[(size_t)row * 32 + 2 * j] = make_uint2(l0u, l1u);
        split_pack(z0, z1, h0, l0u);
        split_pack(z2, z3, h1, l1u);
        *(uint2*)&oh[(size_t)row * 32 + 16 + 2 * j] = make_uint2(h0, h1);
        *(uint2*)&ol[(size_t)row * 32 + 16 + 2 * j] = make_uint2(l0u, l1u);
    } else {
        // ---- vpack path (V transpose + pack, one 64x64 tile per block)
        int vb = blk - RB_QK;
        const int ntile = S_ / 64;            // 32
        int bh = vb / ntile;
        int k0 = (vb - bh * ntile) * 64;
        const float* src = g_v + ((size_t)bh * S_ + k0) * HD_;
        for (int i = tid; i < 64 * 16; i += 256) {
            int r = i >> 4, d4 = (i & 15) << 2;
            *(float4*)&sm[r * VTS + d4] = *(const float4*)&src[r * HD_ + d4];
        }
        __syncthreads();
        for (int i = tid; i < 64 * 32; i += 256) {
            int d = i >> 5, cc = i & 31;
            float v0 = sm[(2 * cc) * VTS + d];
            float v1 = sm[(2 * cc + 1) * VTS + d];
            unsigned hi, lo;
            split_pack(v0, v1, hi, lo);
            size_t o = ((size_t)bh * HD_ + d) * (S_ / 2) + k0 / 2 + cc;
            g_vth[o] = hi; g_vtl[o] = lo;
        }
    }
}

// ---------------- Flash attention (fixed-max exp2, interleaved PV, warp-skip) -----
#define MFIX 16.0f
#define AST 36
#define OFF_Q 0
#define KVBUF 9216
#define OFF_KV 9216
#define ATT_SMEM ((OFF_KV + 2 * KVBUF) * 4)

__global__ __launch_bounds__(256, 2) void attn_tc_kernel(
    const unsigned* __restrict__ Qh, const unsigned* __restrict__ Ql,
    const unsigned* __restrict__ Kh, const unsigned* __restrict__ Kl,
    const unsigned* __restrict__ Vth, const unsigned* __restrict__ Vtl,
    unsigned* __restrict__ Ohg, unsigned* __restrict__ Olg)
{
    extern __shared__ unsigned smu[];
    unsigned* sQh = smu + OFF_Q;
    unsigned* sQl = sQh + 128 * AST;

    const int bh = blockIdx.y;
    const int b = bh / NH_;
    const int h = bh - b * NH_;
    const int kvh = h / (NH_ / NKV_);
    const int q0 = (gridDim.x - 1 - blockIdx.x) * 128;

    const int tid = threadIdx.x;
    const int w = tid >> 5;
    const int lane = tid & 31;
    const int g = lane >> 2;
    const int t = lane & 3;
    const int R0 = w * 16;

    const int a_row = lane & 15;
    const int a_col = (lane >> 4) << 2;
    const int b_row = (((lane >> 4) & 1) << 3) + (lane & 7);
    const int b_col = ((lane >> 3) & 1) << 2;

    const unsigned* Qbh = Qh + ((size_t)bh * S_ + q0) * 32;
    const unsigned* Qbl = Ql + ((size_t)bh * S_ + q0) * 32;
    const unsigned* Kbh = Kh + ((size_t)(b * NKV_ + kvh) * S_) * 32;
    const unsigned* Kbl = Kl + ((size_t)(b * NKV_ + kvh) * S_) * 32;
    const unsigned* Vbh = Vth + (size_t)(b * NKV_ + kvh) * HD_ * (S_ / 2);
    const unsigned* Vbl = Vtl + (size_t)(b * NKV_ + kvh) * HD_ * (S_ / 2);

    const int nkt = q0 / 64 + 2;

    auto issue_kv = [&](int kt, int buf) {
        unsigned* base = smu + OFF_KV + buf * KVBUF;
        unsigned* dKh = base;
        unsigned* dKl = base + 2304;
        unsigned* dVh = base + 4608;
        unsigned* dVl = base + 6912;
        const int k0 = kt * 64;
#pragma unroll
        for (int i = tid; i < 2048; i += 256) {
            int sel = i >> 9;
            int j = i & 511;
            int r = j >> 3, c4 = (j & 7) << 2;
            if (sel == 0)      cp16(&dKh[r * AST + c4], &Kbh[(size_t)(k0 + r) * 32 + c4]);
            else if (sel == 1) cp16(&dKl[r * AST + c4], &Kbl[(size_t)(k0 + r) * 32 + c4]);
            else if (sel == 2) cp16(&dVh[r * AST + c4], &Vbh[(size_t)r * (S_ / 2) + k0 / 2 + c4]);
            else               cp16(&dVl[r * AST + c4], &Vbl[(size_t)r * (S_ / 2) + k0 / 2 + c4]);
        }
    };

#pragma unroll
    for (int i = tid; i < 128 * 8; i += 256) {
        int r = i >> 3, c4 = (i & 7) << 2;
        cp16(&sQh[r * AST + c4], &Qbh[(size_t)r * 32 + c4]);
        cp16(&sQl[r * AST + c4], &Qbl[(size_t)r * 32 + c4]);
    }
    issue_kv(0, 0);
    CP_COMMIT();

    float acc[8][4];
#pragma unroll
    for (int nt = 0; nt < 8; nt++)
#pragma unroll
        for (int r = 0; r < 4; r++) acc[nt][r] = 0.f;

    float l0 = 0.f, l1 = 0.f;

    for (int kt = 0; kt < nkt; kt++) {
        const int k0 = kt * 64;
        if (kt + 1 < nkt) { issue_kv(kt + 1, (kt + 1) & 1); CP_COMMIT(); CP_WAIT1(); }
        else              { CP_WAIT0(); }
        __syncthreads();

        const bool active = !(kt == nkt - 1 && R0 < 49);

        if (active) {
            unsigned* base = smu + OFF_KV + (kt & 1) * KVBUF;
            unsigned* sKh = base;
            unsigned* sKl = base + 2304;
            unsigned* sVh = base + 4608;
            unsigned* sVl = base + 6912;

            float sacc[8][4];
#pragma unroll
            for (int nt = 0; nt < 8; nt++)
#pragma unroll
                for (int r = 0; r < 4; r++) sacc[nt][r] = 0.f;

#pragma unroll
            for (int kk = 0; kk < 4; kk++) {
                const int k8 = kk * 8;
                unsigned qh[4], ql[4];
                ldsm4(qh, &sQh[(R0 + a_row) * AST + k8 + a_col]);
                ldsm4(ql, &sQl[(R0 + a_row) * AST + k8 + a_col]);
#pragma unroll
                for (int np = 0; np < 4; np++) {
                    unsigned kh4[4], kl4[4];
                    ldsm4(kh4, &sKh[(np * 16 + b_row) * AST + k8 + b_col]);
                    ldsm4(kl4, &sKl[(np * 16 + b_row) * AST + k8 + b_col]);
                    mma_split(sacc[2 * np],     qh, ql, kh4,     kl4);
                    mma_split(sacc[2 * np + 1], qh, ql, kh4 + 2, kl4 + 2);
                }
            }

            if (kt >= nkt - 2) {
                int row0 = q0 + R0 + g;
                int row1 = row0 + 8;
#pragma unroll
                for (int nt = 0; nt < 8; nt++) {
                    int col = k0 + nt * 8 + 2 * t;
                    if (col > row0)     sacc[nt][0] = -1e30f;
                    if (col + 1 > row0) sacc[nt][1] = -1e30f;
                    if (col > row1)     sacc[nt][2] = -1e30f;
                    if (col + 1 > row1) sacc[nt][3] = -1e30f;
                }
            }

#pragma unroll
            for (int kk = 0; kk < 4; kk++) {
                float* s0 = sacc[2 * kk];
                float* s1 = sacc[2 * kk + 1];
                s0[0] = exp2f(s0[0] - MFIX);
                s0[1] = exp2f(s0[1] - MFIX);
                s0[2] = exp2f(s0[2] - MFIX);
                s0[3] = exp2f(s0[3] - MFIX);
                s1[0] = exp2f(s1[0] - MFIX);
                s1[1] = exp2f(s1[1] - MFIX);
                s1[2] = exp2f(s1[2] - MFIX);
                s1[3] = exp2f(s1[3] - MFIX);
                l0 += s0[0] + s0[1] + s1[0] + s1[1];
                l1 += s0[2] + s0[3] + s1[2] + s1[3];

                unsigned ph[4], pl[4];
                split_pack(s0[0], s0[1], ph[0], pl[0]);
                split_pack(s0[2], s0[3], ph[1], pl[1]);
                split_pack(s1[0], s1[1], ph[2], pl[2]);
                split_pack(s1[2], s1[3], ph[3], pl[3]);
                const int k8 = kk * 8;
#pragma unroll
                for (int np = 0; np < 4; np++) {
                    unsigned vh4[4], vl4[4];
                    ldsm4(vh4, &sVh[(np * 16 + b_row) * AST + k8 + b_col]);
                    ldsm4(vl4, &sVl[(np * 16 + b_row) * AST + k8 + b_col]);
                    mma_split(acc[2 * np],     ph, pl, vh4,     vl4);
                    mma_split(acc[2 * np + 1], ph, pl, vh4 + 2, vl4 + 2);
                }
            }
        }
        __syncthreads();
    }

    l0 += __shfl_xor_sync(0xffffffffu, l0, 1);
    l0 += __shfl_xor_sync(0xffffffffu, l0, 2);
    l1 += __shfl_xor_sync(0xffffffffu, l1, 1);
    l1 += __shfl_xor_sync(0xffffffffu, l1, 2);

    float inv0 = 1.f / l0;
    float inv1 = 1.f / l1;
    int row0 = q0 + R0 + g;
    int row1 = row0 + 8;
    size_t tok0 = (size_t)b * S_ + row0;
    size_t tok1 = (size_t)b * S_ + row1;
#pragma unroll
    for (int nt = 0; nt < 8; nt++) {
        int col2 = h * 32 + nt * 4 + t;
        unsigned hi, lo;
        split_pack(acc[nt][0] * inv0, acc[nt][1] * inv0, hi, lo);
        Ohg[tok0 * K2_ + col2] = hi;
        Olg[tok0 * K2_ + col2] = lo;
        split_pack(acc[nt][2] * inv1, acc[nt][3] * inv1, hi, lo);
        Ohg[tok1 * K2_ + col2] = hi;
        Olg[tok1 * K2_ + col2] = lo;
    }
}

// ---------------- launch ----------------------------------------------------------
extern "C" void kernel_launch(void* const* d_in, const int* in_sizes, int n_in,
                              void* d_out, int out_size)
{
    const float* x  = (const float*)d_in[0];
    const float* Wq = (const float*)d_in[1];
    const float* Wk = (const float*)d_in[2];
    const float* Wv = (const float*)d_in[3];
    const float* Wo = (const float*)d_in[4];
    float* out = (float*)d_out;

    unsigned *xh, *xl, *wqkvh, *wqkvl, *woh, *wol;
    unsigned *qh, *ql, *kh, *kl, *vth, *vtl, *oh, *ol;
    cudaGetSymbolAddress((void**)&xh, g_xh);       cudaGetSymbolAddress((void**)&xl, g_xl);
    cudaGetSymbolAddress((void**)&wqkvh, g_wqkvh); cudaGetSymbolAddress((void**)&wqkvl, g_wqkvl);
    cudaGetSymbolAddress((void**)&woh, g_woh);     cudaGetSymbolAddress((void**)&wol, g_wol);
    cudaGetSymbolAddress((void**)&qh, g_qh);       cudaGetSymbolAddress((void**)&ql, g_ql);
    cudaGetSymbolAddress((void**)&kh, g_kh);       cudaGetSymbolAddress((void**)&kl, g_kl);
    cudaGetSymbolAddress((void**)&vth, g_vth);     cudaGetSymbolAddress((void**)&vtl, g_vtl);
    cudaGetSymbolAddress((void**)&oh, g_oh);       cudaGetSymbolAddress((void**)&ol, g_ol);

    rope_table_kernel<<<(S_ * 32 + 255) / 256, 256>>>();

    {
        int total = N0 + 2 * N1 + 2 * N2;
        split_pack_all<<<(total + 255) / 256, 256>>>(x, Wq, Wk, Wv, Wo);
    }

    cudaFuncSetAttribute(gemm_tc, cudaFuncAttributeMaxDynamicSharedMemorySize, GEMM_SMEM);

    gemm_tc<<<dim3(NQKV / 64, M_TOK / 128), 256, GEMM_SMEM>>>(xh, xl, wqkvh, wqkvl, nullptr, NQKV, K2_, 0);

    // fused rope(q,k) + vpack
    rope_vpack_kernel<<<RB_QK + VB, 256>>>();

    cudaFuncSetAttribute(attn_tc_kernel, cudaFuncAttributeMaxDynamicSharedMemorySize, ATT_SMEM);
    attn_tc_kernel<<<dim3(S_ / 128, B_ * NH_), 256, ATT_SMEM>>>(qh, ql, kh, kl, vth, vtl, oh, ol);

    gemm_tc<<<dim3(H_ / 64, M_TOK / 128), 256, GEMM_SMEM>>>(oh, ol, woh, wol, out, H_, K2_, 1);
}